// round 1
// baseline (speedup 1.0000x reference)
#include <cuda_runtime.h>

#define UU 256
#define SS 128
#define TT 128
#define BB 256
#define BC 2
#define L2E 1.4426950408889634f

// Packed parameter tables (precomputed each call; deterministic).
__device__ float2 g_ab[UU*UU];    // {-log2e*sigma, +log2e*sigma*mu}
__device__ float  g_we[UU*UU];    // softplus(w) * erev   (den uses |we|)
__device__ float2 g_sab[SS*UU];
__device__ float  g_swe[SS*UU];
__device__ float  g_cmt[UU];
__device__ float  g_gl[UU];
__device__ float  g_glvl[UU];

__device__ __forceinline__ float ex2f(float x){ float y; asm("ex2.approx.ftz.f32 %0, %1;" : "=f"(y) : "f"(x)); return y; }
__device__ __forceinline__ float rcpf(float x){ float y; asm("rcp.approx.ftz.f32 %0, %1;" : "=f"(y) : "f"(x)); return y; }
__device__ __forceinline__ float softplusf(float x){ return log1pf(expf(x)); }

__global__ void prep_kernel(const float* __restrict__ sw,  const float* __restrict__ smu,
                            const float* __restrict__ ssig,const float* __restrict__ serev,
                            const float* __restrict__ w,   const float* __restrict__ mu,
                            const float* __restrict__ sig, const float* __restrict__ erev,
                            const float* __restrict__ gleak, const float* __restrict__ vleak,
                            const float* __restrict__ cm, float* __restrict__ ponder_slot)
{
    int idx = blockIdx.x * blockDim.x + threadIdx.x;
    if (idx < UU*UU) {
        float s = sig[idx];
        g_ab[idx] = make_float2(-L2E*s, L2E*s*mu[idx]);
        g_we[idx] = softplusf(w[idx]) * erev[idx];
    }
    if (idx < SS*UU) {
        float s = ssig[idx];
        g_sab[idx] = make_float2(-L2E*s, L2E*s*smu[idx]);
        g_swe[idx] = softplusf(sw[idx]) * serev[idx];
    }
    if (idx < UU) {
        float g = softplusf(gleak[idx]);
        g_gl[idx]   = g;
        g_glvl[idx] = g * vleak[idx];
        g_cmt[idx]  = softplusf(cm[idx]) * 6.0f;   // softplus(cm) / (1/ODE_UNFOLDS)
    }
    if (idx == 0) *ponder_slot = 0.0f;
}

template<int N> struct IC { static constexpr int value = N; };

__global__ __launch_bounds__(UU, 1) void actltc_main(
    const float* __restrict__ x,
    const float* __restrict__ input_w,  const float* __restrict__ input_b,
    const float* __restrict__ output_w, const float* __restrict__ output_b,
    const float* __restrict__ halt_w,   const float* __restrict__ halt_b,
    float* __restrict__ out)
{
    __shared__ float vbuf[2][BC][UU];
    __shared__ float xin_s[BC][SS];
    __shared__ float red[BC][UU/32];
    __shared__ float logit_s[BC];

    const int j  = threadIdx.x;          // post-synaptic unit (column)
    const int b0 = blockIdx.x * BC;      // first batch element of this CTA

    const float cmt  = g_cmt[j], gl = g_gl[j], glvl = g_glvl[j];
    const float hw   = halt_w[j];
    const float hb   = halt_b[0];
    const float owj  = output_w[j], obj = output_b[j];
    const int   bl   = j >> 7, sl = j & (SS-1);
    const float iws  = input_w[sl], ibs = input_b[sl];

    float v_reg[BC], acc[BC], sn[BC], sd[BC], halt_sum[BC];
    bool  still[BC];
    #pragma unroll
    for (int k = 0; k < BC; k++) { v_reg[k] = 0.f; acc[k] = 0.f; vbuf[0][k][j] = 0.f; }
    int   cur    = 0;
    float ponder = 0.f;
    __syncthreads();

    // One ODE unfold for the batch subset given by compile-time mask M.
    auto unfold = [&](auto MC) {
        constexpr int M = MC.value;
        float num0, den0, num1, den1;
        if constexpr (M & 1) { num0 = sn[0]; den0 = sd[0]; }
        if constexpr (M & 2) { num1 = sn[1]; den1 = sd[1]; }
        const float2* __restrict__ pab = g_ab + j;
        const float*  __restrict__ pwe = g_we + j;
        const float*  __restrict__ v0  = vbuf[cur][0];
        const float*  __restrict__ v1  = vbuf[cur][1];
        #pragma unroll 4
        for (int i = 0; i < UU; i++) {
            float2 abv = pab[(unsigned)i * UU];
            float  wev = pwe[(unsigned)i * UU];
            if constexpr (M & 1) {
                float tt = ex2f(fmaf(abv.x, v0[i], abv.y));   // exp(-sigma*(v-mu))
                float s  = rcpf(1.f + tt);                    // sigmoid
                num0 = fmaf(wev, s, num0);
                den0 = fmaf(fabsf(wev), s, den0);
            }
            if constexpr (M & 2) {
                float tt = ex2f(fmaf(abv.x, v1[i], abv.y));
                float s  = rcpf(1.f + tt);
                num1 = fmaf(wev, s, num1);
                den1 = fmaf(fabsf(wev), s, den1);
            }
        }
        const int nxt = cur ^ 1;
        if constexpr (M & 1) {
            float vn = (fmaf(cmt, v_reg[0], glvl) + num0) * rcpf(cmt + gl + den0 + 1e-8f);
            v_reg[0] = vn; vbuf[nxt][0][j] = vn;
        }
        if constexpr (M & 2) {
            float vn = (fmaf(cmt, v_reg[1], glvl) + num1) * rcpf(cmt + gl + den1 + 1e-8f);
            v_reg[1] = vn; vbuf[nxt][1][j] = vn;
        }
        __syncthreads();
        cur = nxt;
    };

    for (int t = 0; t < TT; t++) {
        // Affine input mapping into smem: xin[b][s]
        xin_s[bl][sl] = fmaf(x[((b0 + bl) * TT + t) * SS + sl], iws, ibs);
        __syncthreads();

        // Sensory sums (hoisted: depend only on xin, not v)
        {
            #pragma unroll
            for (int k = 0; k < BC; k++) { sn[k] = 0.f; sd[k] = 0.f; }
            const float2* __restrict__ pab = g_sab + j;
            const float*  __restrict__ pwe = g_swe + j;
            #pragma unroll 4
            for (int i = 0; i < SS; i++) {
                float2 abv = pab[(unsigned)i * UU];
                float  wev = pwe[(unsigned)i * UU];
                #pragma unroll
                for (int k = 0; k < BC; k++) {
                    float tt = ex2f(fmaf(abv.x, xin_s[k][i], abv.y));
                    float s  = rcpf(1.f + tt);
                    sn[k] = fmaf(wev, s, sn[k]);
                    sd[k] = fmaf(fabsf(wev), s, sd[k]);
                }
            }
        }

        #pragma unroll
        for (int k = 0; k < BC; k++) { acc[k] = 0.f; halt_sum[k] = 0.f; still[k] = true; }

        // ACT loop — skip fully-dead iterations (weight would be 0)
        for (int n = 0; n < 10; n++) {
            int mask = (still[0] ? 1 : 0) | (still[1] ? 2 : 0);
            if (mask == 0) break;
            for (int f = 0; f < 6; f++) {
                if (mask == 3)      unfold(IC<3>{});
                else if (mask == 1) unfold(IC<1>{});
                else                unfold(IC<2>{});
            }
            // Halting logit: reduce v . halt_w over all 256 units
            float c0 = v_reg[0] * hw, c1 = v_reg[1] * hw;
            #pragma unroll
            for (int o = 16; o > 0; o >>= 1) {
                c0 += __shfl_down_sync(0xffffffffu, c0, o);
                c1 += __shfl_down_sync(0xffffffffu, c1, o);
            }
            if ((j & 31) == 0) { red[0][j >> 5] = c0; red[1][j >> 5] = c1; }
            __syncthreads();
            if (j < BC) {
                float s = red[j][0];
                #pragma unroll
                for (int q = 1; q < UU/32; q++) s += red[j][q];
                logit_s[j] = s + hb;
            }
            __syncthreads();
            // ACT bookkeeping (redundant in all threads; identical values)
            #pragma unroll
            for (int k = 0; k < BC; k++) if (still[k]) {
                float p       = rcpf(1.f + ex2f(-L2E * logit_s[k]));
                float new_sum = halt_sum[k] + p;
                bool  halting = (n == 9) || (new_sum >= 0.99f);
                float r       = 1.f - halt_sum[k];
                float wgt     = halting ? r : p;
                acc[k]        = fmaf(wgt, v_reg[k], acc[k]);
                ponder       += 1.f + (halting ? r : 0.f);   // n_updates + remainders
                halt_sum[k]   = new_sum;
                still[k]      = !halting;
            }
        }

        // Per-timestep outputs; new state = acc
        #pragma unroll
        for (int k = 0; k < BC; k++) {
            out[((size_t)(b0 + k) * TT + t) * UU + j] = fmaf(acc[k], owj, obj);
            v_reg[k] = acc[k];
            vbuf[cur][k][j] = acc[k];   // next-t unfold reads this (synced at top of t-loop)
        }
    }

    // Final hidden state
    #pragma unroll
    for (int k = 0; k < BC; k++)
        out[(size_t)BB * TT * UU + (size_t)(b0 + k) * UU + j] = acc[k];

    // Ponder: sum over (b,t) of (n_updates + remainders), then mean over batch
    if (j == 0)
        atomicAdd(out + (size_t)BB * TT * UU + (size_t)BB * UU, ponder * (1.0f / (float)BB));
}

extern "C" void kernel_launch(void* const* d_in, const int* in_sizes, int n_in,
                              void* d_out, int out_size)
{
    const float* x            = (const float*)d_in[0];
    const float* input_w      = (const float*)d_in[1];
    const float* input_b      = (const float*)d_in[2];
    const float* sensory_w    = (const float*)d_in[3];
    const float* sensory_mu   = (const float*)d_in[4];
    const float* sensory_sig  = (const float*)d_in[5];
    const float* sensory_erev = (const float*)d_in[6];
    const float* w            = (const float*)d_in[7];
    const float* mu           = (const float*)d_in[8];
    const float* sigma        = (const float*)d_in[9];
    const float* erev         = (const float*)d_in[10];
    const float* gleak        = (const float*)d_in[11];
    const float* vleak        = (const float*)d_in[12];
    const float* cm           = (const float*)d_in[13];
    const float* output_w     = (const float*)d_in[14];
    const float* output_b     = (const float*)d_in[15];
    const float* halt_w       = (const float*)d_in[16];
    const float* halt_b       = (const float*)d_in[17];
    float* out = (float*)d_out;

    float* ponder_slot = out + (size_t)BB * TT * UU + (size_t)BB * UU;

    prep_kernel<<<(UU*UU + 255) / 256, 256>>>(
        sensory_w, sensory_mu, sensory_sig, sensory_erev,
        w, mu, sigma, erev, gleak, vleak, cm, ponder_slot);

    actltc_main<<<BB / BC, UU>>>(
        x, input_w, input_b, output_w, output_b, halt_w, halt_b, out);
}

// round 2
// speedup vs baseline: 1.0040x; 1.0040x over previous
#include <cuda_runtime.h>

#define UU 256
#define SS 128
#define TT 128
#define BB 256
#define BC 2
#define L2E 1.4426950408889634f

// Packed parameter tables (precomputed each call; deterministic).
__device__ float2 g_ab[UU*UU];    // {-log2e*sigma, +log2e*sigma*mu}
__device__ float  g_we[UU*UU];    // softplus(w) * erev   (den uses |we|)
__device__ float2 g_sab[SS*UU];
__device__ float  g_swe[SS*UU];
__device__ float  g_cmt[UU];
__device__ float  g_gl[UU];
__device__ float  g_glvl[UU];

__device__ __forceinline__ float ex2f(float x){ float y; asm("ex2.approx.ftz.f32 %0, %1;" : "=f"(y) : "f"(x)); return y; }
__device__ __forceinline__ float rcpf(float x){ float y; asm("rcp.approx.ftz.f32 %0, %1;" : "=f"(y) : "f"(x)); return y; }
__device__ __forceinline__ float softplusf(float x){ return log1pf(expf(x)); }

__global__ void prep_kernel(const float* __restrict__ sw,  const float* __restrict__ smu,
                            const float* __restrict__ ssig,const float* __restrict__ serev,
                            const float* __restrict__ w,   const float* __restrict__ mu,
                            const float* __restrict__ sig, const float* __restrict__ erev,
                            const float* __restrict__ gleak, const float* __restrict__ vleak,
                            const float* __restrict__ cm, float* __restrict__ ponder_slot)
{
    int idx = blockIdx.x * blockDim.x + threadIdx.x;
    if (idx < UU*UU) {
        float s = sig[idx];
        g_ab[idx] = make_float2(-L2E*s, L2E*s*mu[idx]);
        g_we[idx] = softplusf(w[idx]) * erev[idx];
    }
    if (idx < SS*UU) {
        float s = ssig[idx];
        g_sab[idx] = make_float2(-L2E*s, L2E*s*smu[idx]);
        g_swe[idx] = softplusf(sw[idx]) * serev[idx];
    }
    if (idx < UU) {
        float g = softplusf(gleak[idx]);
        g_gl[idx]   = g;
        g_glvl[idx] = g * vleak[idx];
        g_cmt[idx]  = softplusf(cm[idx]) * 6.0f;   // softplus(cm) / (1/ODE_UNFOLDS)
    }
    if (idx == 0) *ponder_slot = 0.0f;
}

template<int N> struct IC { static constexpr int value = N; };

__global__ __launch_bounds__(UU, 1) void actltc_main(
    const float* __restrict__ x,
    const float* __restrict__ input_w,  const float* __restrict__ input_b,
    const float* __restrict__ output_w, const float* __restrict__ output_b,
    const float* __restrict__ halt_w,   const float* __restrict__ halt_b,
    float* __restrict__ out)
{
    __shared__ float vbuf[2][BC][UU];
    __shared__ float xin_s[BC][SS];
    __shared__ float red[BC][UU/32];
    __shared__ float logit_s[BC];

    const int j  = threadIdx.x;          // post-synaptic unit (column)
    const int b0 = blockIdx.x * BC;      // first batch element of this CTA

    const float cmt  = g_cmt[j], gl = g_gl[j], glvl = g_glvl[j];
    const float hw   = halt_w[j];
    const float hb   = halt_b[0];
    const float owj  = output_w[j], obj = output_b[j];
    const int   bl   = j >> 7, sl = j & (SS-1);
    const float iws  = input_w[sl], ibs = input_b[sl];

    float v_reg[BC], acc[BC], sn[BC], sd[BC], halt_sum[BC];
    bool  still[BC];
    #pragma unroll
    for (int k = 0; k < BC; k++) { v_reg[k] = 0.f; acc[k] = 0.f; vbuf[0][k][j] = 0.f; }
    int   cur    = 0;
    float ponder = 0.f;
    __syncthreads();

    // One ODE unfold for the batch subset given by compile-time mask M.
    auto unfold = [&](auto MC) {
        constexpr int M = MC.value;
        float num0, den0, num1, den1;
        if constexpr (M & 1) { num0 = sn[0]; den0 = sd[0]; }
        if constexpr (M & 2) { num1 = sn[1]; den1 = sd[1]; }
        const float2* __restrict__ pab = g_ab + j;
        const float*  __restrict__ pwe = g_we + j;
        const float*  __restrict__ v0  = vbuf[cur][0];
        const float*  __restrict__ v1  = vbuf[cur][1];
        #pragma unroll 4
        for (int i = 0; i < UU; i++) {
            float2 abv = pab[(unsigned)i * UU];
            float  wev = pwe[(unsigned)i * UU];
            if constexpr (M & 1) {
                float tt = ex2f(fmaf(abv.x, v0[i], abv.y));   // exp(-sigma*(v-mu))
                float s  = rcpf(1.f + tt);                    // sigmoid
                num0 = fmaf(wev, s, num0);
                den0 = fmaf(fabsf(wev), s, den0);
            }
            if constexpr (M & 2) {
                float tt = ex2f(fmaf(abv.x, v1[i], abv.y));
                float s  = rcpf(1.f + tt);
                num1 = fmaf(wev, s, num1);
                den1 = fmaf(fabsf(wev), s, den1);
            }
        }
        const int nxt = cur ^ 1;
        if constexpr (M & 1) {
            float vn = (fmaf(cmt, v_reg[0], glvl) + num0) * rcpf(cmt + gl + den0 + 1e-8f);
            v_reg[0] = vn; vbuf[nxt][0][j] = vn;
        }
        if constexpr (M & 2) {
            float vn = (fmaf(cmt, v_reg[1], glvl) + num1) * rcpf(cmt + gl + den1 + 1e-8f);
            v_reg[1] = vn; vbuf[nxt][1][j] = vn;
        }
        __syncthreads();
        cur = nxt;
    };

    for (int t = 0; t < TT; t++) {
        // Affine input mapping into smem: xin[b][s]
        xin_s[bl][sl] = fmaf(x[((b0 + bl) * TT + t) * SS + sl], iws, ibs);
        __syncthreads();

        // Sensory sums (hoisted: depend only on xin, not v)
        {
            #pragma unroll
            for (int k = 0; k < BC; k++) { sn[k] = 0.f; sd[k] = 0.f; }
            const float2* __restrict__ pab = g_sab + j;
            const float*  __restrict__ pwe = g_swe + j;
            #pragma unroll 4
            for (int i = 0; i < SS; i++) {
                float2 abv = pab[(unsigned)i * UU];
                float  wev = pwe[(unsigned)i * UU];
                #pragma unroll
                for (int k = 0; k < BC; k++) {
                    float tt = ex2f(fmaf(abv.x, xin_s[k][i], abv.y));
                    float s  = rcpf(1.f + tt);
                    sn[k] = fmaf(wev, s, sn[k]);
                    sd[k] = fmaf(fabsf(wev), s, sd[k]);
                }
            }
        }

        #pragma unroll
        for (int k = 0; k < BC; k++) { acc[k] = 0.f; halt_sum[k] = 0.f; still[k] = true; }

        // ACT loop — skip fully-dead iterations (weight would be 0)
        for (int n = 0; n < 10; n++) {
            int mask = (still[0] ? 1 : 0) | (still[1] ? 2 : 0);
            if (mask == 0) break;
            for (int f = 0; f < 6; f++) {
                if (mask == 3)      unfold(IC<3>{});
                else if (mask == 1) unfold(IC<1>{});
                else                unfold(IC<2>{});
            }
            // Halting logit: reduce v . halt_w over all 256 units
            float c0 = v_reg[0] * hw, c1 = v_reg[1] * hw;
            #pragma unroll
            for (int o = 16; o > 0; o >>= 1) {
                c0 += __shfl_down_sync(0xffffffffu, c0, o);
                c1 += __shfl_down_sync(0xffffffffu, c1, o);
            }
            if ((j & 31) == 0) { red[0][j >> 5] = c0; red[1][j >> 5] = c1; }
            __syncthreads();
            if (j < BC) {
                float s = red[j][0];
                #pragma unroll
                for (int q = 1; q < UU/32; q++) s += red[j][q];
                logit_s[j] = s + hb;
            }
            __syncthreads();
            // ACT bookkeeping (redundant in all threads; identical values)
            #pragma unroll
            for (int k = 0; k < BC; k++) if (still[k]) {
                float p       = rcpf(1.f + ex2f(-L2E * logit_s[k]));
                float new_sum = halt_sum[k] + p;
                bool  halting = (n == 9) || (new_sum >= 0.99f);
                float r       = 1.f - halt_sum[k];
                float wgt     = halting ? r : p;
                acc[k]        = fmaf(wgt, v_reg[k], acc[k]);
                ponder       += 1.f + (halting ? r : 0.f);   // n_updates + remainders
                halt_sum[k]   = new_sum;
                still[k]      = !halting;
            }
        }

        // Per-timestep outputs; new state = acc
        #pragma unroll
        for (int k = 0; k < BC; k++) {
            out[((size_t)(b0 + k) * TT + t) * UU + j] = fmaf(acc[k], owj, obj);
            v_reg[k] = acc[k];
            vbuf[cur][k][j] = acc[k];   // next-t unfold reads this (synced at top of t-loop)
        }
    }

    // Final hidden state
    #pragma unroll
    for (int k = 0; k < BC; k++)
        out[(size_t)BB * TT * UU + (size_t)(b0 + k) * UU + j] = acc[k];

    // Ponder: sum over (b,t) of (n_updates + remainders), then mean over batch
    if (j == 0)
        atomicAdd(out + (size_t)BB * TT * UU + (size_t)BB * UU, ponder * (1.0f / (float)BB));
}

extern "C" void kernel_launch(void* const* d_in, const int* in_sizes, int n_in,
                              void* d_out, int out_size)
{
    const float* x            = (const float*)d_in[0];
    const float* input_w      = (const float*)d_in[1];
    const float* input_b      = (const float*)d_in[2];
    const float* sensory_w    = (const float*)d_in[3];
    const float* sensory_mu   = (const float*)d_in[4];
    const float* sensory_sig  = (const float*)d_in[5];
    const float* sensory_erev = (const float*)d_in[6];
    const float* w            = (const float*)d_in[7];
    const float* mu           = (const float*)d_in[8];
    const float* sigma        = (const float*)d_in[9];
    const float* erev         = (const float*)d_in[10];
    const float* gleak        = (const float*)d_in[11];
    const float* vleak        = (const float*)d_in[12];
    const float* cm           = (const float*)d_in[13];
    const float* output_w     = (const float*)d_in[14];
    const float* output_b     = (const float*)d_in[15];
    const float* halt_w       = (const float*)d_in[16];
    const float* halt_b       = (const float*)d_in[17];
    float* out = (float*)d_out;

    float* ponder_slot = out + (size_t)BB * TT * UU + (size_t)BB * UU;

    prep_kernel<<<(UU*UU + 255) / 256, 256>>>(
        sensory_w, sensory_mu, sensory_sig, sensory_erev,
        w, mu, sigma, erev, gleak, vleak, cm, ponder_slot);

    actltc_main<<<BB / BC, UU>>>(
        x, input_w, input_b, output_w, output_b, halt_w, halt_b, out);
}

// round 3
// speedup vs baseline: 1.7504x; 1.7435x over previous
#include <cuda_runtime.h>

#define UU 256
#define SS 128
#define TT 128
#define BB 256
#define BC 2
#define TPB 512
#define IH  (UU/2)   // i-range per half (recurrent)
#define ISH (SS/2)   // i-range per half (sensory)
#define L2E 1.4426950408889634f

// Packed parameter tables (precomputed each call; deterministic).
__device__ float2 g_ab[UU*UU];    // {-log2e*sigma, +log2e*sigma*mu}
__device__ float  g_we[UU*UU];    // softplus(w) * erev   (den uses |we|)
__device__ float2 g_sab[SS*UU];
__device__ float  g_swe[SS*UU];
__device__ float  g_cmt[UU];
__device__ float  g_gl[UU];
__device__ float  g_glvl[UU];

__device__ __forceinline__ float ex2f(float x){ float y; asm("ex2.approx.ftz.f32 %0, %1;" : "=f"(y) : "f"(x)); return y; }
__device__ __forceinline__ float rcpf(float x){ float y; asm("rcp.approx.ftz.f32 %0, %1;" : "=f"(y) : "f"(x)); return y; }
__device__ __forceinline__ float softplusf(float x){ return log1pf(expf(x)); }

__global__ void prep_kernel(const float* __restrict__ sw,  const float* __restrict__ smu,
                            const float* __restrict__ ssig,const float* __restrict__ serev,
                            const float* __restrict__ w,   const float* __restrict__ mu,
                            const float* __restrict__ sig, const float* __restrict__ erev,
                            const float* __restrict__ gleak, const float* __restrict__ vleak,
                            const float* __restrict__ cm, float* __restrict__ ponder_slot)
{
    int idx = blockIdx.x * blockDim.x + threadIdx.x;
    if (idx < UU*UU) {
        float s = sig[idx];
        g_ab[idx] = make_float2(-L2E*s, L2E*s*mu[idx]);
        g_we[idx] = softplusf(w[idx]) * erev[idx];
    }
    if (idx < SS*UU) {
        float s = ssig[idx];
        g_sab[idx] = make_float2(-L2E*s, L2E*s*smu[idx]);
        g_swe[idx] = softplusf(sw[idx]) * serev[idx];
    }
    if (idx < UU) {
        float g = softplusf(gleak[idx]);
        g_gl[idx]   = g;
        g_glvl[idx] = g * vleak[idx];
        g_cmt[idx]  = softplusf(cm[idx]) * 6.0f;   // softplus(cm) / (1/ODE_UNFOLDS)
    }
    if (idx == 0) *ponder_slot = 0.0f;
}

template<int N> struct IC { static constexpr int value = N; };

__global__ __launch_bounds__(TPB, 1) void actltc_main(
    const float* __restrict__ x,
    const float* __restrict__ input_w,  const float* __restrict__ input_b,
    const float* __restrict__ output_w, const float* __restrict__ output_b,
    const float* __restrict__ halt_w,   const float* __restrict__ halt_b,
    float* __restrict__ out)
{
    __shared__ float vbuf[2][BC][UU];
    __shared__ float xin_s[BC][SS];
    __shared__ float pn[2][BC][UU];     // partial num per half
    __shared__ float pd[2][BC][UU];     // partial den per half
    __shared__ float red[BC][UU/32];
    __shared__ float logit_s[BC];

    const int tid = threadIdx.x;
    const int j   = tid & (UU-1);        // post-synaptic unit (column)
    const int h   = tid >> 8;            // i-range half
    const int b0  = blockIdx.x * BC;     // first batch element of this CTA

    const float cmt  = g_cmt[j], gl = g_gl[j], glvl = g_glvl[j];
    const float hw   = halt_w[j];
    const float hb   = halt_b[0];
    const float owj  = output_w[j], obj = output_b[j];

    float v_reg[BC], acc[BC], sn[BC], sd[BC], halt_sum[BC];
    bool  still[BC];
    #pragma unroll
    for (int k = 0; k < BC; k++) { v_reg[k] = 0.f; acc[k] = 0.f; }
    if (h == 0) { vbuf[0][0][j] = 0.f; vbuf[0][1][j] = 0.f; }
    int   cur    = 0;
    float ponder = 0.f;
    __syncthreads();

    // One ODE unfold for the batch subset given by compile-time mask M.
    // Each half computes a 128-wide partial; combined via smem (2 barriers).
    auto unfold = [&](auto MC) {
        constexpr int M = MC.value;
        float num0 = 0.f, den0 = 0.f, num1 = 0.f, den1 = 0.f;
        const float2* __restrict__ pab = g_ab + j + (unsigned)(h * IH) * UU;
        const float*  __restrict__ pwe = g_we + j + (unsigned)(h * IH) * UU;
        const float*  __restrict__ v0  = vbuf[cur][0] + h * IH;
        const float*  __restrict__ v1  = vbuf[cur][1] + h * IH;
        #pragma unroll 4
        for (int i = 0; i < IH; i++) {
            float2 abv = pab[(unsigned)i * UU];
            float  wev = pwe[(unsigned)i * UU];
            if constexpr (M & 1) {
                float tt = ex2f(fmaf(abv.x, v0[i], abv.y));   // exp(-sigma*(v-mu))
                float s  = rcpf(1.f + tt);                    // sigmoid
                num0 = fmaf(wev, s, num0);
                den0 = fmaf(fabsf(wev), s, den0);
            }
            if constexpr (M & 2) {
                float tt = ex2f(fmaf(abv.x, v1[i], abv.y));
                float s  = rcpf(1.f + tt);
                num1 = fmaf(wev, s, num1);
                den1 = fmaf(fabsf(wev), s, den1);
            }
        }
        if constexpr (M & 1) { pn[h][0][j] = num0; pd[h][0][j] = den0; }
        if constexpr (M & 2) { pn[h][1][j] = num1; pd[h][1][j] = den1; }
        __syncthreads();
        const int nxt = cur ^ 1;
        if constexpr (M & 1) {
            float nm = pn[0][0][j] + pn[1][0][j] + sn[0];
            float dn = pd[0][0][j] + pd[1][0][j] + sd[0];
            float vn = (fmaf(cmt, v_reg[0], glvl) + nm) * rcpf(cmt + gl + dn + 1e-8f);
            v_reg[0] = vn; if (h == 0) vbuf[nxt][0][j] = vn;
        }
        if constexpr (M & 2) {
            float nm = pn[0][1][j] + pn[1][1][j] + sn[1];
            float dn = pd[0][1][j] + pd[1][1][j] + sd[1];
            float vn = (fmaf(cmt, v_reg[1], glvl) + nm) * rcpf(cmt + gl + dn + 1e-8f);
            v_reg[1] = vn; if (h == 0) vbuf[nxt][1][j] = vn;
        }
        __syncthreads();
        cur = nxt;
    };

    for (int t = 0; t < TT; t++) {
        // Affine input mapping into smem: xin[b][s] (first 256 threads)
        if (tid < BC * SS) {
            int bl = tid >> 7, sl = tid & (SS-1);
            xin_s[bl][sl] = fmaf(x[((b0 + bl) * TT + t) * SS + sl], input_w[sl], input_b[sl]);
        }
        __syncthreads();

        // Sensory sums (hoisted: depend only on xin, not v), i-split 2-way
        {
            float s0n = 0.f, s0d = 0.f, s1n = 0.f, s1d = 0.f;
            const float2* __restrict__ pab = g_sab + j + (unsigned)(h * ISH) * UU;
            const float*  __restrict__ pwe = g_swe + j + (unsigned)(h * ISH) * UU;
            const float*  __restrict__ x0  = xin_s[0] + h * ISH;
            const float*  __restrict__ x1  = xin_s[1] + h * ISH;
            #pragma unroll 4
            for (int i = 0; i < ISH; i++) {
                float2 abv = pab[(unsigned)i * UU];
                float  wev = pwe[(unsigned)i * UU];
                float  aw  = fabsf(wev);
                float t0 = ex2f(fmaf(abv.x, x0[i], abv.y));
                float q0 = rcpf(1.f + t0);
                s0n = fmaf(wev, q0, s0n);  s0d = fmaf(aw, q0, s0d);
                float t1 = ex2f(fmaf(abv.x, x1[i], abv.y));
                float q1 = rcpf(1.f + t1);
                s1n = fmaf(wev, q1, s1n);  s1d = fmaf(aw, q1, s1d);
            }
            pn[h][0][j] = s0n; pd[h][0][j] = s0d;
            pn[h][1][j] = s1n; pd[h][1][j] = s1d;
            __syncthreads();
            sn[0] = pn[0][0][j] + pn[1][0][j];  sd[0] = pd[0][0][j] + pd[1][0][j];
            sn[1] = pn[0][1][j] + pn[1][1][j];  sd[1] = pd[0][1][j] + pd[1][1][j];
            __syncthreads();   // protect pn/pd before unfold overwrites them
        }

        #pragma unroll
        for (int k = 0; k < BC; k++) { acc[k] = 0.f; halt_sum[k] = 0.f; still[k] = true; }

        // ACT loop — skip fully-dead iterations (weight would be 0)
        for (int n = 0; n < 10; n++) {
            int mask = (still[0] ? 1 : 0) | (still[1] ? 2 : 0);
            if (mask == 0) break;
            for (int f = 0; f < 6; f++) {
                if (mask == 3)      unfold(IC<3>{});
                else if (mask == 1) unfold(IC<1>{});
                else                unfold(IC<2>{});
            }
            // Halting logit: reduce v . halt_w over 256 units (h==0 warps only)
            if (h == 0) {
                float c0 = v_reg[0] * hw, c1 = v_reg[1] * hw;
                #pragma unroll
                for (int o = 16; o > 0; o >>= 1) {
                    c0 += __shfl_down_sync(0xffffffffu, c0, o);
                    c1 += __shfl_down_sync(0xffffffffu, c1, o);
                }
                if ((j & 31) == 0) { red[0][j >> 5] = c0; red[1][j >> 5] = c1; }
            }
            __syncthreads();
            if (tid < BC) {
                float s = red[tid][0];
                #pragma unroll
                for (int q = 1; q < UU/32; q++) s += red[tid][q];
                logit_s[tid] = s + hb;
            }
            __syncthreads();
            // ACT bookkeeping (redundant in all threads; identical values)
            #pragma unroll
            for (int k = 0; k < BC; k++) if (still[k]) {
                float p       = rcpf(1.f + ex2f(-L2E * logit_s[k]));
                float new_sum = halt_sum[k] + p;
                bool  halting = (n == 9) || (new_sum >= 0.99f);
                float r       = 1.f - halt_sum[k];
                float wgt     = halting ? r : p;
                acc[k]        = fmaf(wgt, v_reg[k], acc[k]);
                ponder       += 1.f + (halting ? r : 0.f);   // n_updates + remainders
                halt_sum[k]   = new_sum;
                still[k]      = !halting;
            }
        }

        // Per-timestep outputs; new state = acc
        #pragma unroll
        for (int k = 0; k < BC; k++) {
            if (h == 0) {
                out[((size_t)(b0 + k) * TT + t) * UU + j] = fmaf(acc[k], owj, obj);
                vbuf[cur][k][j] = acc[k];   // next-t unfold reads this (synced at top of t-loop)
            }
            v_reg[k] = acc[k];
        }
    }

    // Final hidden state
    if (h == 0) {
        #pragma unroll
        for (int k = 0; k < BC; k++)
            out[(size_t)BB * TT * UU + (size_t)(b0 + k) * UU + j] = acc[k];
    }

    // Ponder: sum over (b,t) of (n_updates + remainders), then mean over batch
    if (tid == 0)
        atomicAdd(out + (size_t)BB * TT * UU + (size_t)BB * UU, ponder * (1.0f / (float)BB));
}

extern "C" void kernel_launch(void* const* d_in, const int* in_sizes, int n_in,
                              void* d_out, int out_size)
{
    const float* x            = (const float*)d_in[0];
    const float* input_w      = (const float*)d_in[1];
    const float* input_b      = (const float*)d_in[2];
    const float* sensory_w    = (const float*)d_in[3];
    const float* sensory_mu   = (const float*)d_in[4];
    const float* sensory_sig  = (const float*)d_in[5];
    const float* sensory_erev = (const float*)d_in[6];
    const float* w            = (const float*)d_in[7];
    const float* mu           = (const float*)d_in[8];
    const float* sigma        = (const float*)d_in[9];
    const float* erev         = (const float*)d_in[10];
    const float* gleak        = (const float*)d_in[11];
    const float* vleak        = (const float*)d_in[12];
    const float* cm           = (const float*)d_in[13];
    const float* output_w     = (const float*)d_in[14];
    const float* output_b     = (const float*)d_in[15];
    const float* halt_w       = (const float*)d_in[16];
    const float* halt_b       = (const float*)d_in[17];
    float* out = (float*)d_out;

    float* ponder_slot = out + (size_t)BB * TT * UU + (size_t)BB * UU;

    prep_kernel<<<(UU*UU + 255) / 256, 256>>>(
        sensory_w, sensory_mu, sensory_sig, sensory_erev,
        w, mu, sigma, erev, gleak, vleak, cm, ponder_slot);

    actltc_main<<<BB / BC, TPB>>>(
        x, input_w, input_b, output_w, output_b, halt_w, halt_b, out);
}

// round 5
// speedup vs baseline: 2.4215x; 1.3834x over previous
#include <cuda_runtime.h>

#define UU 256
#define SS 128
#define TT 128
#define BB 256
#define BC 2
#define TPB 1024
#define NQ 4
#define IH  (UU/NQ)   // 64 recurrent i per quarter
#define ISH (SS/NQ)   // 32 sensory i per quarter

// Packed parameter tables (precomputed each call; deterministic).
__device__ float2 g_ab[UU*UU];    // {0.5*sigma, -0.5*sigma*mu}  (tanh-form argument)
__device__ float  g_we[UU*UU];    // softplus(w) * erev
__device__ float2 g_sab[SS*UU];
__device__ float  g_swe[SS*UU];
__device__ float  g_cmt[UU];
__device__ float  g_gl[UU];
__device__ float  g_glvl[UU];
__device__ float  g_gnc[UU];      // gl*vleak + 0.5*sum_i we[i][j]
__device__ float  g_k2[UU];       // cmt + gl + 1e-8 + 0.5*sum_i |we[i][j]|
__device__ float  g_scn[UU];      // 0.5*sum_i swe[i][j]
__device__ float  g_scd[UU];      // 0.5*sum_i |swe[i][j]|

__device__ __forceinline__ float tanhfast(float x){ float y; asm("tanh.approx.f32 %0, %1;" : "=f"(y) : "f"(x)); return y; }
__device__ __forceinline__ float rcpf(float x){ float y; asm("rcp.approx.ftz.f32 %0, %1;" : "=f"(y) : "f"(x)); return y; }
__device__ __forceinline__ float softplusf(float x){ return log1pf(expf(x)); }

__global__ void prep_kernel(const float* __restrict__ sw,  const float* __restrict__ smu,
                            const float* __restrict__ ssig,const float* __restrict__ serev,
                            const float* __restrict__ w,   const float* __restrict__ mu,
                            const float* __restrict__ sig, const float* __restrict__ erev,
                            const float* __restrict__ gleak, const float* __restrict__ vleak,
                            const float* __restrict__ cm, float* __restrict__ ponder_slot)
{
    int idx = blockIdx.x * blockDim.x + threadIdx.x;
    if (idx < UU*UU) {
        float s = sig[idx];
        g_ab[idx] = make_float2(0.5f*s, -0.5f*s*mu[idx]);
        g_we[idx] = softplusf(w[idx]) * erev[idx];
    }
    if (idx < SS*UU) {
        float s = ssig[idx];
        g_sab[idx] = make_float2(0.5f*s, -0.5f*s*smu[idx]);
        g_swe[idx] = softplusf(sw[idx]) * serev[idx];
    }
    if (idx < UU) {
        float g = softplusf(gleak[idx]);
        g_gl[idx]   = g;
        g_glvl[idx] = g * vleak[idx];
        g_cmt[idx]  = softplusf(cm[idx]) * 6.0f;   // softplus(cm) / (1/ODE_UNFOLDS)
    }
    if (idx == 0) *ponder_slot = 0.0f;
}

// Fold the tanh-identity constants (0.5*sum of weights) into per-j leak terms.
__global__ void prep2_kernel()
{
    int j = threadIdx.x;            // 256 threads
    float cn = 0.f, cd = 0.f;
    for (int i = 0; i < UU; i++) {
        float v = g_we[(unsigned)i * UU + j];
        cn += v; cd += fabsf(v);
    }
    float scn = 0.f, scd = 0.f;
    for (int i = 0; i < SS; i++) {
        float v = g_swe[(unsigned)i * UU + j];
        scn += v; scd += fabsf(v);
    }
    g_gnc[j] = g_glvl[j] + 0.5f * cn;
    g_k2[j]  = g_cmt[j] + g_gl[j] + 1e-8f + 0.5f * cd;
    g_scn[j] = 0.5f * scn;
    g_scd[j] = 0.5f * scd;
}

template<int N> struct IC { static constexpr int value = N; };

__global__ __launch_bounds__(TPB, 1) void actltc_main(
    const float* __restrict__ x,
    const float* __restrict__ input_w,  const float* __restrict__ input_b,
    const float* __restrict__ output_w, const float* __restrict__ output_b,
    const float* __restrict__ halt_w,   const float* __restrict__ halt_b,
    float* __restrict__ out)
{
    __shared__ float vbuf[2][BC][UU];
    __shared__ float xin_s[BC][SS];
    __shared__ float pn[NQ][BC][UU];    // partial sum(we*tanh) per quarter
    __shared__ float pd[NQ][BC][UU];    // partial sum(|we|*tanh) per quarter
    __shared__ float red[BC][UU/32];
    __shared__ float logit_s[BC];

    const int tid = threadIdx.x;
    const int j   = tid & (UU-1);        // post-synaptic unit (column)
    const int q   = tid >> 8;            // i-range quarter
    const int b0  = blockIdx.x * BC;     // first batch element of this CTA

    const float cmt = g_cmt[j], gnc = g_gnc[j], k2 = g_k2[j];
    const float hw  = halt_w[j];
    const float hb  = halt_b[0];

    float v_reg[BC], acc[BC], sn[BC], sd[BC], halt_sum[BC];
    bool  still[BC];
    #pragma unroll
    for (int k = 0; k < BC; k++) { v_reg[k] = 0.f; acc[k] = 0.f; }
    if (q == 0) { vbuf[0][0][j] = 0.f; vbuf[0][1][j] = 0.f; }
    int   cur    = 0;
    float ponder = 0.f;
    __syncthreads();

    // One ODE unfold for the batch subset given by compile-time mask M.
    // Each quarter computes a 64-wide partial; combined via smem (2 barriers).
    auto unfold = [&](auto MC) {
        constexpr int M = MC.value;
        float num0 = 0.f, den0 = 0.f, num1 = 0.f, den1 = 0.f;
        const float2* __restrict__ pab = g_ab + j + (unsigned)(q * IH) * UU;
        const float*  __restrict__ pwe = g_we + j + (unsigned)(q * IH) * UU;
        const float*  __restrict__ v0  = vbuf[cur][0] + q * IH;
        const float*  __restrict__ v1  = vbuf[cur][1] + q * IH;
        #pragma unroll 4
        for (int i = 0; i < IH; i++) {
            float2 abv = pab[(unsigned)i * UU];
            float  wev = pwe[(unsigned)i * UU];
            float  aw  = fabsf(wev);
            if constexpr (M & 1) {
                float th = tanhfast(fmaf(abv.x, v0[i], abv.y));
                num0 = fmaf(wev, th, num0);
                den0 = fmaf(aw,  th, den0);
            }
            if constexpr (M & 2) {
                float th = tanhfast(fmaf(abv.x, v1[i], abv.y));
                num1 = fmaf(wev, th, num1);
                den1 = fmaf(aw,  th, den1);
            }
        }
        if constexpr (M & 1) { pn[q][0][j] = num0; pd[q][0][j] = den0; }
        if constexpr (M & 2) { pn[q][1][j] = num1; pd[q][1][j] = den1; }
        __syncthreads();
        const int nxt = cur ^ 1;
        if constexpr (M & 1) {
            float nm = (pn[0][0][j] + pn[1][0][j]) + (pn[2][0][j] + pn[3][0][j]);
            float dn = (pd[0][0][j] + pd[1][0][j]) + (pd[2][0][j] + pd[3][0][j]);
            nm = fmaf(0.5f, nm, sn[0]);
            dn = fmaf(0.5f, dn, sd[0]);
            float vn = (fmaf(cmt, v_reg[0], gnc) + nm) * rcpf(k2 + dn);
            v_reg[0] = vn; if (q == 0) vbuf[nxt][0][j] = vn;
        }
        if constexpr (M & 2) {
            float nm = (pn[0][1][j] + pn[1][1][j]) + (pn[2][1][j] + pn[3][1][j]);
            float dn = (pd[0][1][j] + pd[1][1][j]) + (pd[2][1][j] + pd[3][1][j]);
            nm = fmaf(0.5f, nm, sn[1]);
            dn = fmaf(0.5f, dn, sd[1]);
            float vn = (fmaf(cmt, v_reg[1], gnc) + nm) * rcpf(k2 + dn);
            v_reg[1] = vn; if (q == 0) vbuf[nxt][1][j] = vn;
        }
        __syncthreads();
        cur = nxt;
    };

    for (int t = 0; t < TT; t++) {
        // Affine input mapping into smem: xin[b][s] (first 256 threads)
        if (tid < BC * SS) {
            int bl = tid >> 7, sl = tid & (SS-1);
            xin_s[bl][sl] = fmaf(x[((b0 + bl) * TT + t) * SS + sl], input_w[sl], input_b[sl]);
        }
        __syncthreads();

        // Sensory sums (hoisted: depend only on xin, not v), i-split 4-way
        {
            float s0n = 0.f, s0d = 0.f, s1n = 0.f, s1d = 0.f;
            const float2* __restrict__ pab = g_sab + j + (unsigned)(q * ISH) * UU;
            const float*  __restrict__ pwe = g_swe + j + (unsigned)(q * ISH) * UU;
            const float*  __restrict__ x0  = xin_s[0] + q * ISH;
            const float*  __restrict__ x1  = xin_s[1] + q * ISH;
            #pragma unroll 4
            for (int i = 0; i < ISH; i++) {
                float2 abv = pab[(unsigned)i * UU];
                float  wev = pwe[(unsigned)i * UU];
                float  aw  = fabsf(wev);
                float t0 = tanhfast(fmaf(abv.x, x0[i], abv.y));
                s0n = fmaf(wev, t0, s0n);  s0d = fmaf(aw, t0, s0d);
                float t1 = tanhfast(fmaf(abv.x, x1[i], abv.y));
                s1n = fmaf(wev, t1, s1n);  s1d = fmaf(aw, t1, s1d);
            }
            pn[q][0][j] = s0n; pd[q][0][j] = s0d;
            pn[q][1][j] = s1n; pd[q][1][j] = s1d;
            __syncthreads();
            sn[0] = fmaf(0.5f, (pn[0][0][j]+pn[1][0][j]) + (pn[2][0][j]+pn[3][0][j]), g_scn[j]);
            sd[0] = fmaf(0.5f, (pd[0][0][j]+pd[1][0][j]) + (pd[2][0][j]+pd[3][0][j]), g_scd[j]);
            sn[1] = fmaf(0.5f, (pn[0][1][j]+pn[1][1][j]) + (pn[2][1][j]+pn[3][1][j]), g_scn[j]);
            sd[1] = fmaf(0.5f, (pd[0][1][j]+pd[1][1][j]) + (pd[2][1][j]+pd[3][1][j]), g_scd[j]);
            __syncthreads();   // protect pn/pd before unfold overwrites them
        }

        #pragma unroll
        for (int k = 0; k < BC; k++) { acc[k] = 0.f; halt_sum[k] = 0.f; still[k] = true; }

        // ACT loop — skip fully-dead iterations (weight would be 0)
        for (int n = 0; n < 10; n++) {
            int mask = (still[0] ? 1 : 0) | (still[1] ? 2 : 0);
            if (mask == 0) break;
            for (int f = 0; f < 6; f++) {
                if (mask == 3)      unfold(IC<3>{});
                else if (mask == 1) unfold(IC<1>{});
                else                unfold(IC<2>{});
            }
            // Halting logit: reduce v . halt_w over 256 units (q==0 warps only)
            if (q == 0) {
                float c0 = v_reg[0] * hw, c1 = v_reg[1] * hw;
                #pragma unroll
                for (int o = 16; o > 0; o >>= 1) {
                    c0 += __shfl_down_sync(0xffffffffu, c0, o);
                    c1 += __shfl_down_sync(0xffffffffu, c1, o);
                }
                if ((j & 31) == 0) { red[0][j >> 5] = c0; red[1][j >> 5] = c1; }
            }
            __syncthreads();
            if (tid < BC) {
                float s = red[tid][0];
                #pragma unroll
                for (int w = 1; w < UU/32; w++) s += red[tid][w];
                logit_s[tid] = s + hb;
            }
            __syncthreads();
            // ACT bookkeeping (redundant in all threads; identical values)
            #pragma unroll
            for (int k = 0; k < BC; k++) if (still[k]) {
                float p       = fmaf(0.5f, tanhfast(0.5f * logit_s[k]), 0.5f);  // sigmoid
                float new_sum = halt_sum[k] + p;
                bool  halting = (n == 9) || (new_sum >= 0.99f);
                float r       = 1.f - halt_sum[k];
                float wgt     = halting ? r : p;
                acc[k]        = fmaf(wgt, v_reg[k], acc[k]);
                ponder       += 1.f + (halting ? r : 0.f);   // n_updates + remainders
                halt_sum[k]   = new_sum;
                still[k]      = !halting;
            }
        }

        // Per-timestep outputs; new state = acc
        #pragma unroll
        for (int k = 0; k < BC; k++) {
            if (q == 0) {
                out[((size_t)(b0 + k) * TT + t) * UU + j] = fmaf(acc[k], output_w[j], output_b[j]);
                vbuf[cur][k][j] = acc[k];   // next-t unfold reads this (synced at top of t-loop)
            }
            v_reg[k] = acc[k];
        }
    }

    // Final hidden state
    if (q == 0) {
        #pragma unroll
        for (int k = 0; k < BC; k++)
            out[(size_t)BB * TT * UU + (size_t)(b0 + k) * UU + j] = acc[k];
    }

    // Ponder: sum over (b,t) of (n_updates + remainders), then mean over batch
    if (tid == 0)
        atomicAdd(out + (size_t)BB * TT * UU + (size_t)BB * UU, ponder * (1.0f / (float)BB));
}

extern "C" void kernel_launch(void* const* d_in, const int* in_sizes, int n_in,
                              void* d_out, int out_size)
{
    const float* x            = (const float*)d_in[0];
    const float* input_w      = (const float*)d_in[1];
    const float* input_b      = (const float*)d_in[2];
    const float* sensory_w    = (const float*)d_in[3];
    const float* sensory_mu   = (const float*)d_in[4];
    const float* sensory_sig  = (const float*)d_in[5];
    const float* sensory_erev = (const float*)d_in[6];
    const float* w            = (const float*)d_in[7];
    const float* mu           = (const float*)d_in[8];
    const float* sigma        = (const float*)d_in[9];
    const float* erev         = (const float*)d_in[10];
    const float* gleak        = (const float*)d_in[11];
    const float* vleak        = (const float*)d_in[12];
    const float* cm           = (const float*)d_in[13];
    const float* output_w     = (const float*)d_in[14];
    const float* output_b     = (const float*)d_in[15];
    const float* halt_w       = (const float*)d_in[16];
    const float* halt_b       = (const float*)d_in[17];
    float* out = (float*)d_out;

    float* ponder_slot = out + (size_t)BB * TT * UU + (size_t)BB * UU;

    prep_kernel<<<(UU*UU + 255) / 256, 256>>>(
        sensory_w, sensory_mu, sensory_sig, sensory_erev,
        w, mu, sigma, erev, gleak, vleak, cm, ponder_slot);

    prep2_kernel<<<1, UU>>>();

    actltc_main<<<BB / BC, TPB>>>(
        x, input_w, input_b, output_w, output_b, halt_w, halt_b, out);
}

// round 7
// speedup vs baseline: 2.7860x; 1.1505x over previous
#include <cuda_runtime.h>
#include <cuda_fp16.h>

#define UU 256
#define SS 128
#define TT 128
#define BB 256
#define BC 2
#define TPB 1024
#define NQ 4
#define IH  (UU/NQ)   // 64 recurrent i per quarter
#define ISH (SS/NQ)   // 32 sensory i per quarter

// Packed 8-byte parameter element: {half2 (a,b), fp32 we}
//   a = 0.5*sigma, b = -0.5*sigma*mu  (tanh-form argument coeffs)
//   we = softplus(w) * erev
struct __align__(8) P8 { __half2 ab; float we; };

__device__ P8    g_rp[UU*UU];
__device__ P8    g_sp[SS*UU];
__device__ float g_cmt[UU];
__device__ float g_gl[UU];
__device__ float g_glvl[UU];

__device__ __forceinline__ float tanhfast(float x){ float y; asm("tanh.approx.f32 %0, %1;" : "=f"(y) : "f"(x)); return y; }
__device__ __forceinline__ float rcpf(float x){ float y; asm("rcp.approx.ftz.f32 %0, %1;" : "=f"(y) : "f"(x)); return y; }
__device__ __forceinline__ float softplusf(float x){ return log1pf(expf(x)); }

__global__ void prep_kernel(const float* __restrict__ sw,  const float* __restrict__ smu,
                            const float* __restrict__ ssig,const float* __restrict__ serev,
                            const float* __restrict__ w,   const float* __restrict__ mu,
                            const float* __restrict__ sig, const float* __restrict__ erev,
                            const float* __restrict__ gleak, const float* __restrict__ vleak,
                            const float* __restrict__ cm, float* __restrict__ ponder_slot)
{
    int idx = blockIdx.x * blockDim.x + threadIdx.x;
    if (idx < UU*UU) {
        float s = sig[idx];
        g_rp[idx].ab = __floats2half2_rn(0.5f*s, -0.5f*s*mu[idx]);
        g_rp[idx].we = softplusf(w[idx]) * erev[idx];
    }
    if (idx < SS*UU) {
        float s = ssig[idx];
        g_sp[idx].ab = __floats2half2_rn(0.5f*s, -0.5f*s*smu[idx]);
        g_sp[idx].we = softplusf(sw[idx]) * serev[idx];
    }
    if (idx < UU) {
        float g = softplusf(gleak[idx]);
        g_gl[idx]   = g;
        g_glvl[idx] = g * vleak[idx];
        g_cmt[idx]  = softplusf(cm[idx]) * 6.0f;   // softplus(cm) / (1/ODE_UNFOLDS)
    }
    if (idx == 0) *ponder_slot = 0.0f;
}

template<int N> struct IC { static constexpr int value = N; };

__global__ __launch_bounds__(TPB, 1) void actltc_main(
    const float* __restrict__ x,
    const float* __restrict__ input_w,  const float* __restrict__ input_b,
    const float* __restrict__ output_w, const float* __restrict__ output_b,
    const float* __restrict__ halt_w,   const float* __restrict__ halt_b,
    float* __restrict__ out)
{
    __shared__ float vbuf[2][BC][UU];
    __shared__ float xin_s[BC][SS];
    __shared__ float pn[NQ][BC][UU];    // partial sum(we*tanh) per quarter
    __shared__ float pd[NQ][BC][UU];    // partial sum(|we|*tanh) per quarter
    __shared__ float red[BC][UU/32];
    __shared__ float logit_s[BC];

    const int tid = threadIdx.x;
    const int j   = tid & (UU-1);        // post-synaptic unit (column)
    const int q   = tid >> 8;            // i-range quarter
    const int b0  = blockIdx.x * BC;     // first batch element of this CTA

    const float2* __restrict__ rp2 = (const float2*)g_rp;
    const float2* __restrict__ sp2 = (const float2*)g_sp;

    // ---- Preamble: fold tanh-identity constants (0.5*sum of weights) per j.
    // Each (j,q) thread sums its i-slice; combined through pn/pd smem.
    {
        float cn = 0.f, cd = 0.f;
        const P8* __restrict__ pr = g_rp + j + (unsigned)(q * IH) * UU;
        #pragma unroll 8
        for (int i = 0; i < IH; i++) {
            float v = pr[(unsigned)i * UU].we;
            cn += v; cd += fabsf(v);
        }
        float scn = 0.f, scd = 0.f;
        const P8* __restrict__ ps = g_sp + j + (unsigned)(q * ISH) * UU;
        #pragma unroll 8
        for (int i = 0; i < ISH; i++) {
            float v = ps[(unsigned)i * UU].we;
            scn += v; scd += fabsf(v);
        }
        pn[q][0][j] = cn;  pd[q][0][j] = cd;
        pn[q][1][j] = scn; pd[q][1][j] = scd;
    }
    __syncthreads();
    const float cmt = g_cmt[j];
    const float gnc = g_glvl[j] + 0.5f * ((pn[0][0][j]+pn[1][0][j]) + (pn[2][0][j]+pn[3][0][j]));
    const float k2  = cmt + g_gl[j] + 1e-8f
                    + 0.5f * ((pd[0][0][j]+pd[1][0][j]) + (pd[2][0][j]+pd[3][0][j]));
    const float scn0 = 0.5f * ((pn[0][1][j]+pn[1][1][j]) + (pn[2][1][j]+pn[3][1][j]));
    const float scd0 = 0.5f * ((pd[0][1][j]+pd[1][1][j]) + (pd[2][1][j]+pd[3][1][j]));
    const float hw  = halt_w[j];
    const float hb  = halt_b[0];
    __syncthreads();

    float v_reg[BC], acc[BC], sn[BC], sd[BC], halt_sum[BC];
    bool  still[BC];
    #pragma unroll
    for (int k = 0; k < BC; k++) { v_reg[k] = 0.f; acc[k] = 0.f; }
    if (q == 0) { vbuf[0][0][j] = 0.f; vbuf[0][1][j] = 0.f; }
    int   cur    = 0;
    float ponder = 0.f;
    __syncthreads();

    // One ODE unfold for the batch subset given by compile-time mask M.
    // Each quarter computes a 64-wide partial; combined via smem (2 barriers).
    auto unfold = [&](auto MC) {
        constexpr int M = MC.value;
        float num0 = 0.f, den0 = 0.f, num1 = 0.f, den1 = 0.f;
        const float2* __restrict__ pr = rp2 + j + (unsigned)(q * IH) * UU;
        const float*  __restrict__ v0 = vbuf[cur][0] + q * IH;
        const float*  __restrict__ v1 = vbuf[cur][1] + q * IH;
        #pragma unroll 4
        for (int i = 0; i < IH; i++) {
            float2 raw = pr[(unsigned)i * UU];                  // one LDG.64
            float2 abf = __half22float2(*reinterpret_cast<const __half2*>(&raw.x));
            float  wev = raw.y;
            float  aw  = fabsf(wev);
            if constexpr (M & 1) {
                float th = tanhfast(fmaf(abf.x, v0[i], abf.y));
                num0 = fmaf(wev, th, num0);
                den0 = fmaf(aw,  th, den0);
            }
            if constexpr (M & 2) {
                float th = tanhfast(fmaf(abf.x, v1[i], abf.y));
                num1 = fmaf(wev, th, num1);
                den1 = fmaf(aw,  th, den1);
            }
        }
        if constexpr (M & 1) { pn[q][0][j] = num0; pd[q][0][j] = den0; }
        if constexpr (M & 2) { pn[q][1][j] = num1; pd[q][1][j] = den1; }
        __syncthreads();
        const int nxt = cur ^ 1;
        if constexpr (M & 1) {
            float nm = (pn[0][0][j] + pn[1][0][j]) + (pn[2][0][j] + pn[3][0][j]);
            float dn = (pd[0][0][j] + pd[1][0][j]) + (pd[2][0][j] + pd[3][0][j]);
            nm = fmaf(0.5f, nm, sn[0]);
            dn = fmaf(0.5f, dn, sd[0]);
            float vn = (fmaf(cmt, v_reg[0], gnc) + nm) * rcpf(k2 + dn);
            v_reg[0] = vn; if (q == 0) vbuf[nxt][0][j] = vn;
        }
        if constexpr (M & 2) {
            float nm = (pn[0][1][j] + pn[1][1][j]) + (pn[2][1][j] + pn[3][1][j]);
            float dn = (pd[0][1][j] + pd[1][1][j]) + (pd[2][1][j] + pd[3][1][j]);
            nm = fmaf(0.5f, nm, sn[1]);
            dn = fmaf(0.5f, dn, sd[1]);
            float vn = (fmaf(cmt, v_reg[1], gnc) + nm) * rcpf(k2 + dn);
            v_reg[1] = vn; if (q == 0) vbuf[nxt][1][j] = vn;
        }
        __syncthreads();
        cur = nxt;
    };

    for (int t = 0; t < TT; t++) {
        // Affine input mapping into smem: xin[b][s] (first 256 threads)
        if (tid < BC * SS) {
            int bl = tid >> 7, sl = tid & (SS-1);
            xin_s[bl][sl] = fmaf(x[((b0 + bl) * TT + t) * SS + sl], input_w[sl], input_b[sl]);
        }
        __syncthreads();

        // Sensory sums (hoisted: depend only on xin, not v), i-split 4-way
        {
            float s0n = 0.f, s0d = 0.f, s1n = 0.f, s1d = 0.f;
            const float2* __restrict__ ps = sp2 + j + (unsigned)(q * ISH) * UU;
            const float*  __restrict__ x0 = xin_s[0] + q * ISH;
            const float*  __restrict__ x1 = xin_s[1] + q * ISH;
            #pragma unroll 4
            for (int i = 0; i < ISH; i++) {
                float2 raw = ps[(unsigned)i * UU];
                float2 abf = __half22float2(*reinterpret_cast<const __half2*>(&raw.x));
                float  wev = raw.y;
                float  aw  = fabsf(wev);
                float t0 = tanhfast(fmaf(abf.x, x0[i], abf.y));
                s0n = fmaf(wev, t0, s0n);  s0d = fmaf(aw, t0, s0d);
                float t1 = tanhfast(fmaf(abf.x, x1[i], abf.y));
                s1n = fmaf(wev, t1, s1n);  s1d = fmaf(aw, t1, s1d);
            }
            pn[q][0][j] = s0n; pd[q][0][j] = s0d;
            pn[q][1][j] = s1n; pd[q][1][j] = s1d;
            __syncthreads();
            sn[0] = fmaf(0.5f, (pn[0][0][j]+pn[1][0][j]) + (pn[2][0][j]+pn[3][0][j]), scn0);
            sd[0] = fmaf(0.5f, (pd[0][0][j]+pd[1][0][j]) + (pd[2][0][j]+pd[3][0][j]), scd0);
            sn[1] = fmaf(0.5f, (pn[0][1][j]+pn[1][1][j]) + (pn[2][1][j]+pn[3][1][j]), scn0);
            sd[1] = fmaf(0.5f, (pd[0][1][j]+pd[1][1][j]) + (pd[2][1][j]+pd[3][1][j]), scd0);
            __syncthreads();   // protect pn/pd before unfold overwrites them
        }

        #pragma unroll
        for (int k = 0; k < BC; k++) { acc[k] = 0.f; halt_sum[k] = 0.f; still[k] = true; }

        // ACT loop — skip fully-dead iterations (weight would be 0)
        for (int n = 0; n < 10; n++) {
            int mask = (still[0] ? 1 : 0) | (still[1] ? 2 : 0);
            if (mask == 0) break;
            for (int f = 0; f < 6; f++) {
                if (mask == 3)      unfold(IC<3>{});
                else if (mask == 1) unfold(IC<1>{});
                else                unfold(IC<2>{});
            }
            // Halting logit: reduce v . halt_w over 256 units (q==0 warps only)
            if (q == 0) {
                float c0 = v_reg[0] * hw, c1 = v_reg[1] * hw;
                #pragma unroll
                for (int o = 16; o > 0; o >>= 1) {
                    c0 += __shfl_down_sync(0xffffffffu, c0, o);
                    c1 += __shfl_down_sync(0xffffffffu, c1, o);
                }
                if ((j & 31) == 0) { red[0][j >> 5] = c0; red[1][j >> 5] = c1; }
            }
            __syncthreads();
            if (tid < BC) {
                float s = red[tid][0];
                #pragma unroll
                for (int w = 1; w < UU/32; w++) s += red[tid][w];
                logit_s[tid] = s + hb;
            }
            __syncthreads();
            // ACT bookkeeping (redundant in all threads; identical values)
            #pragma unroll
            for (int k = 0; k < BC; k++) if (still[k]) {
                float p       = fmaf(0.5f, tanhfast(0.5f * logit_s[k]), 0.5f);  // sigmoid
                float new_sum = halt_sum[k] + p;
                bool  halting = (n == 9) || (new_sum >= 0.99f);
                float r       = 1.f - halt_sum[k];
                float wgt     = halting ? r : p;
                acc[k]        = fmaf(wgt, v_reg[k], acc[k]);
                ponder       += 1.f + (halting ? r : 0.f);   // n_updates + remainders
                halt_sum[k]   = new_sum;
                still[k]      = !halting;
            }
        }

        // Per-timestep outputs; new state = acc
        #pragma unroll
        for (int k = 0; k < BC; k++) {
            if (q == 0) {
                out[((size_t)(b0 + k) * TT + t) * UU + j] = fmaf(acc[k], output_w[j], output_b[j]);
                vbuf[cur][k][j] = acc[k];   // next-t unfold reads this (synced at top of t-loop)
            }
            v_reg[k] = acc[k];
        }
    }

    // Final hidden state
    if (q == 0) {
        #pragma unroll
        for (int k = 0; k < BC; k++)
            out[(size_t)BB * TT * UU + (size_t)(b0 + k) * UU + j] = acc[k];
    }

    // Ponder: sum over (b,t) of (n_updates + remainders), then mean over batch
    if (tid == 0)
        atomicAdd(out + (size_t)BB * TT * UU + (size_t)BB * UU, ponder * (1.0f / (float)BB));
}

extern "C" void kernel_launch(void* const* d_in, const int* in_sizes, int n_in,
                              void* d_out, int out_size)
{
    const float* x            = (const float*)d_in[0];
    const float* input_w      = (const float*)d_in[1];
    const float* input_b      = (const float*)d_in[2];
    const float* sensory_w    = (const float*)d_in[3];
    const float* sensory_mu   = (const float*)d_in[4];
    const float* sensory_sig  = (const float*)d_in[5];
    const float* sensory_erev = (const float*)d_in[6];
    const float* w            = (const float*)d_in[7];
    const float* mu           = (const float*)d_in[8];
    const float* sigma        = (const float*)d_in[9];
    const float* erev         = (const float*)d_in[10];
    const float* gleak        = (const float*)d_in[11];
    const float* vleak        = (const float*)d_in[12];
    const float* cm           = (const float*)d_in[13];
    const float* output_w     = (const float*)d_in[14];
    const float* output_b     = (const float*)d_in[15];
    const float* halt_w       = (const float*)d_in[16];
    const float* halt_b       = (const float*)d_in[17];
    float* out = (float*)d_out;

    float* ponder_slot = out + (size_t)BB * TT * UU + (size_t)BB * UU;

    prep_kernel<<<(UU*UU + 255) / 256, 256>>>(
        sensory_w, sensory_mu, sensory_sig, sensory_erev,
        w, mu, sigma, erev, gleak, vleak, cm, ponder_slot);

    actltc_main<<<BB / BC, TPB>>>(
        x, input_w, input_b, output_w, output_b, halt_w, halt_b, out);
}